// round 3
// baseline (speedup 1.0000x reference)
#include <cuda_runtime.h>

// Problem dims (fixed by the dataset)
#define BB   64
#define CC   512
#define NN   1024
#define CQ   64
#define RTOT 640   // Wq(64) + Wk(64) + Wv(512) rows

// Scratch: Y holds f (rows 0..63), g (rows 64..127), h (rows 128..639) per batch.
// scores holds scores then beta in-place.
__device__ float d_Y[(size_t)BB * RTOT * NN];        // 167.8 MB
__device__ float d_scores[(size_t)BB * NN * NN];     // 268.4 MB

// ---------------------------------------------------------------------------
// K1: Y[b][r][n] = sum_c W[r][c] * x[b][c][n],  W = [Wq; Wk; Wv]
// 128x128 tile, kc=8, 8x8 microtile, 256 threads.
// A (weights) is K-contiguous -> transposed smem store. B (x) loads direct.
// ---------------------------------------------------------------------------
__global__ __launch_bounds__(256) void qkv_gemm(
    const float* __restrict__ x,
    const float* __restrict__ Wq,
    const float* __restrict__ Wk,
    const float* __restrict__ Wv)
{
    __shared__ float As[8][128];
    __shared__ float Bs[8][128];

    const int b    = blockIdx.z;
    const int row0 = blockIdx.y * 128;
    const int col0 = blockIdx.x * 128;
    const float* xb = x + (size_t)b * CC * NN;

    const int tid = threadIdx.x;
    const int ty = tid >> 4;       // 0..15
    const int tx = tid & 15;       // 0..15

    float acc[8][8];
#pragma unroll
    for (int i = 0; i < 8; i++)
#pragma unroll
        for (int j = 0; j < 8; j++) acc[i][j] = 0.0f;

    // A-load mapping: row = tid>>1 (0..127), k-quad = (tid&1)*4
    const int arl = tid >> 1;
    const int ar  = row0 + arl;
    const float* wrow = (ar < CQ)     ? (Wq + (size_t)ar * CC)
                      : (ar < 2 * CQ) ? (Wk + (size_t)(ar - CQ) * CC)
                                      : (Wv + (size_t)(ar - 2 * CQ) * CC);
    const int ak4 = (tid & 1) * 4;
    // B-load mapping: k-row = tid>>5 (0..7), col-quad = (tid&31)*4
    const int brow = tid >> 5;
    const int bcol = (tid & 31) * 4;

    for (int k0 = 0; k0 < CC; k0 += 8) {
        float4 av = *(const float4*)(wrow + k0 + ak4);
        As[ak4 + 0][arl] = av.x;
        As[ak4 + 1][arl] = av.y;
        As[ak4 + 2][arl] = av.z;
        As[ak4 + 3][arl] = av.w;
        float4 bv = *(const float4*)(xb + (size_t)(k0 + brow) * NN + col0 + bcol);
        *(float4*)&Bs[brow][bcol] = bv;
        __syncthreads();
#pragma unroll
        for (int kk = 0; kk < 8; kk++) {
            float a[8], bfr[8];
#pragma unroll
            for (int i = 0; i < 8; i++) a[i] = As[kk][ty * 8 + i];
#pragma unroll
            for (int j = 0; j < 8; j++) bfr[j] = Bs[kk][tx * 8 + j];
#pragma unroll
            for (int i = 0; i < 8; i++)
#pragma unroll
                for (int j = 0; j < 8; j++)
                    acc[i][j] += a[i] * bfr[j];
        }
        __syncthreads();
    }

    float* yb = d_Y + (size_t)b * RTOT * NN;
#pragma unroll
    for (int i = 0; i < 8; i++) {
        const int r = row0 + ty * 8 + i;
#pragma unroll
        for (int j = 0; j < 8; j += 4) {
            float4 v = make_float4(acc[i][j], acc[i][j + 1], acc[i][j + 2], acc[i][j + 3]);
            *(float4*)(yb + (size_t)r * NN + col0 + tx * 8 + j) = v;
        }
    }
}

// ---------------------------------------------------------------------------
// K2: scores[b][i][j] = leaky( sum_q F[b][q][i] * G[b][q][j] ), K = 64.
// Both operands are [K-row, contiguous-col] -> direct smem loads.
// ---------------------------------------------------------------------------
__global__ __launch_bounds__(256) void scores_gemm()
{
    __shared__ float As[8][128];
    __shared__ float Bs[8][128];

    const int b  = blockIdx.z;
    const int i0 = blockIdx.y * 128;
    const int j0 = blockIdx.x * 128;
    const float* F = d_Y + (size_t)b * RTOT * NN;            // rows 0..63
    const float* G = F + (size_t)CQ * NN;                    // rows 64..127

    const int tid = threadIdx.x;
    const int ty = tid >> 4, tx = tid & 15;
    const int krow = tid >> 5;          // 0..7
    const int cq4  = (tid & 31) * 4;

    float acc[8][8];
#pragma unroll
    for (int i = 0; i < 8; i++)
#pragma unroll
        for (int j = 0; j < 8; j++) acc[i][j] = 0.0f;

    for (int k0 = 0; k0 < CQ; k0 += 8) {
        *(float4*)&As[krow][cq4] = *(const float4*)(F + (size_t)(k0 + krow) * NN + i0 + cq4);
        *(float4*)&Bs[krow][cq4] = *(const float4*)(G + (size_t)(k0 + krow) * NN + j0 + cq4);
        __syncthreads();
#pragma unroll
        for (int kk = 0; kk < 8; kk++) {
            float a[8], bfr[8];
#pragma unroll
            for (int i = 0; i < 8; i++) a[i] = As[kk][ty * 8 + i];
#pragma unroll
            for (int j = 0; j < 8; j++) bfr[j] = Bs[kk][tx * 8 + j];
#pragma unroll
            for (int i = 0; i < 8; i++)
#pragma unroll
                for (int j = 0; j < 8; j++)
                    acc[i][j] += a[i] * bfr[j];
        }
        __syncthreads();
    }

    float* S = d_scores + (size_t)b * NN * NN;
#pragma unroll
    for (int i = 0; i < 8; i++) {
        const int ri = i0 + ty * 8 + i;
#pragma unroll
        for (int j = 0; j < 8; j += 4) {
            float4 v;
            float s0 = acc[i][j + 0], s1 = acc[i][j + 1], s2 = acc[i][j + 2], s3 = acc[i][j + 3];
            v.x = s0 >= 0.0f ? s0 : 0.2f * s0;
            v.y = s1 >= 0.0f ? s1 : 0.2f * s1;
            v.z = s2 >= 0.0f ? s2 : 0.2f * s2;
            v.w = s3 >= 0.0f ? s3 : 0.2f * s3;
            *(float4*)(S + (size_t)ri * NN + j0 + tx * 8 + j) = v;
        }
    }
}

// ---------------------------------------------------------------------------
// K3: column softmax (over i) + mask renorm, in place.
// beta[i][j] = mask[i]*exp(s[i][j]-m_j) / (Smask_j + EPS*Z_j)
// One thread per column j (coalesced). 3 streaming passes.
// ---------------------------------------------------------------------------
__global__ __launch_bounds__(256) void softmax_kernel(const float* __restrict__ mask)
{
    const int b = blockIdx.y;
    const int j = blockIdx.x * 256 + threadIdx.x;
    float* S = d_scores + (size_t)b * NN * NN;
    const float* mb = mask + (size_t)b * NN;

    // pass 1: max over i (4 independent chains)
    float m0 = -1e30f, m1 = -1e30f, m2 = -1e30f, m3 = -1e30f;
    for (int i = 0; i < NN; i += 4) {
        m0 = fmaxf(m0, S[(size_t)(i + 0) * NN + j]);
        m1 = fmaxf(m1, S[(size_t)(i + 1) * NN + j]);
        m2 = fmaxf(m2, S[(size_t)(i + 2) * NN + j]);
        m3 = fmaxf(m3, S[(size_t)(i + 3) * NN + j]);
    }
    const float mx = fmaxf(fmaxf(m0, m1), fmaxf(m2, m3));

    // pass 2: Z = sum exp, Sm = sum mask*exp (4 independent accumulators)
    float z0 = 0, z1 = 0, z2 = 0, z3 = 0;
    float s0 = 0, s1 = 0, s2 = 0, s3 = 0;
    for (int i = 0; i < NN; i += 4) {
        float e0 = __expf(S[(size_t)(i + 0) * NN + j] - mx);
        float e1 = __expf(S[(size_t)(i + 1) * NN + j] - mx);
        float e2 = __expf(S[(size_t)(i + 2) * NN + j] - mx);
        float e3 = __expf(S[(size_t)(i + 3) * NN + j] - mx);
        z0 += e0; z1 += e1; z2 += e2; z3 += e3;
        s0 += __ldg(&mb[i + 0]) * e0;
        s1 += __ldg(&mb[i + 1]) * e1;
        s2 += __ldg(&mb[i + 2]) * e2;
        s3 += __ldg(&mb[i + 3]) * e3;
    }
    const float Z  = (z0 + z1) + (z2 + z3);
    const float Sm = (s0 + s1) + (s2 + s3);
    const float inv = 1.0f / (Sm + 1e-6f * Z);

    // pass 3: write beta in place
    for (int i = 0; i < NN; i++) {
        float e = __expf(S[(size_t)i * NN + j] - mx);
        S[(size_t)i * NN + j] = __ldg(&mb[i]) * e * inv;
    }
}

// ---------------------------------------------------------------------------
// K4: out[b][c][m] = gamma * (sum_n h[b][c][n]*beta[b][n][m]) * mask[b][m] + x[b][c][m]
// A = h: K-contiguous -> transposed smem store. B = beta: direct loads.
// ---------------------------------------------------------------------------
__global__ __launch_bounds__(256) void out_gemm(
    const float* __restrict__ x,
    const float* __restrict__ mask,
    const float* __restrict__ gamma,
    float* __restrict__ out)
{
    __shared__ float As[8][128];
    __shared__ float Bs[8][128];

    const int b  = blockIdx.z;
    const int c0 = blockIdx.y * 128;
    const int m0 = blockIdx.x * 128;
    const float* h  = d_Y + (size_t)b * RTOT * NN + (size_t)(2 * CQ) * NN; // rows 128..
    const float* Bt = d_scores + (size_t)b * NN * NN;                      // beta[n][m]

    const int tid = threadIdx.x;
    const int ty = tid >> 4, tx = tid & 15;

    float acc[8][8];
#pragma unroll
    for (int i = 0; i < 8; i++)
#pragma unroll
        for (int j = 0; j < 8; j++) acc[i][j] = 0.0f;

    const int arl = tid >> 1;                       // 0..127 (c within tile)
    const float* hrow = h + (size_t)(c0 + arl) * NN;
    const int ak4 = (tid & 1) * 4;
    const int brow = tid >> 5;
    const int bcol = (tid & 31) * 4;

    for (int k0 = 0; k0 < NN; k0 += 8) {
        float4 av = *(const float4*)(hrow + k0 + ak4);
        As[ak4 + 0][arl] = av.x;
        As[ak4 + 1][arl] = av.y;
        As[ak4 + 2][arl] = av.z;
        As[ak4 + 3][arl] = av.w;
        float4 bv = *(const float4*)(Bt + (size_t)(k0 + brow) * NN + m0 + bcol);
        *(float4*)&Bs[brow][bcol] = bv;
        __syncthreads();
#pragma unroll
        for (int kk = 0; kk < 8; kk++) {
            float a[8], bfr[8];
#pragma unroll
            for (int i = 0; i < 8; i++) a[i] = As[kk][ty * 8 + i];
#pragma unroll
            for (int j = 0; j < 8; j++) bfr[j] = Bs[kk][tx * 8 + j];
#pragma unroll
            for (int i = 0; i < 8; i++)
#pragma unroll
                for (int j = 0; j < 8; j++)
                    acc[i][j] += a[i] * bfr[j];
        }
        __syncthreads();
    }

    const float g0 = gamma[0];
    const float* xb = x + (size_t)b * CC * NN;
    float* ob = out + (size_t)b * CC * NN;
    const float* mb = mask + (size_t)b * NN;

#pragma unroll
    for (int i = 0; i < 8; i++) {
        const int c = c0 + ty * 8 + i;
#pragma unroll
        for (int j = 0; j < 8; j += 4) {
            const int m = m0 + tx * 8 + j;
            float4 xv = *(const float4*)(xb + (size_t)c * NN + m);
            float4 mv = *(const float4*)(mb + m);
            float4 v;
            v.x = g0 * acc[i][j + 0] * mv.x + xv.x;
            v.y = g0 * acc[i][j + 1] * mv.y + xv.y;
            v.z = g0 * acc[i][j + 2] * mv.z + xv.z;
            v.w = g0 * acc[i][j + 3] * mv.w + xv.w;
            *(float4*)(ob + (size_t)c * NN + m) = v;
        }
    }
}

// ---------------------------------------------------------------------------
extern "C" void kernel_launch(void* const* d_in, const int* in_sizes, int n_in,
                              void* d_out, int out_size)
{
    const float* x     = (const float*)d_in[0];
    const float* mask  = (const float*)d_in[1];
    const float* Wq    = (const float*)d_in[2];
    const float* Wk    = (const float*)d_in[3];
    const float* Wv    = (const float*)d_in[4];
    const float* gamma = (const float*)d_in[5];
    float* out = (float*)d_out;

    {
        dim3 grid(NN / 128, RTOT / 128, BB);
        qkv_gemm<<<grid, 256>>>(x, Wq, Wk, Wv);
    }
    {
        dim3 grid(NN / 128, NN / 128, BB);
        scores_gemm<<<grid, 256>>>();
    }
    {
        dim3 grid(NN / 256, BB);
        softmax_kernel<<<grid, 256>>>(mask);
    }
    {
        dim3 grid(NN / 128, CC / 128, BB);
        out_gemm<<<grid, 256>>>(x, mask, gamma, out);
    }
}

// round 4
// speedup vs baseline: 1.8944x; 1.8944x over previous
#include <cuda_runtime.h>
#include <cstdint>

// Problem dims (fixed by the dataset)
#define BB   64
#define CC   512
#define NN   1024
#define CQ   64
#define RTOT 640   // Wq(64) + Wk(64) + Wv(512) rows

// Scratch: Y holds f (rows 0..63), g (rows 64..127), h (rows 128..639) per batch.
// scores holds scores then beta in-place.
__device__ float d_Y[(size_t)BB * RTOT * NN];        // 167.8 MB
__device__ float d_scores[(size_t)BB * NN * NN];     // 268.4 MB

// ---------------------------------------------------------------------------
// tf32 helpers
// ---------------------------------------------------------------------------
__device__ __forceinline__ uint32_t f2tf(float f) {
    uint32_t u;
    asm("cvt.rna.tf32.f32 %0, %1;" : "=r"(u) : "f"(f));
    return u;
}

__device__ __forceinline__ void mma8(float4& d, const uint32_t a[4], const uint32_t b[2]) {
    asm volatile(
        "mma.sync.aligned.m16n8k8.row.col.f32.tf32.tf32.f32 "
        "{%0,%1,%2,%3}, {%4,%5,%6,%7}, {%8,%9}, {%0,%1,%2,%3};"
        : "+f"(d.x), "+f"(d.y), "+f"(d.z), "+f"(d.w)
        : "r"(a[0]), "r"(a[1]), "r"(a[2]), "r"(a[3]), "r"(b[0]), "r"(b[1]));
}

// ---------------------------------------------------------------------------
// Shared inner compute: one 16-deep k-chunk over a 128x128 block tile.
// smem layout: As[16][132] (k-major, m contiguous), Bs[16][132] (k-major, n contig)
// Warp tile 64x32: 4 m-frags (16 rows) x 4 n-frags (8 cols).
// SPLIT=true -> 3xTF32 (near-fp32); SPLIT=false -> single tf32.
// ---------------------------------------------------------------------------
template<bool SPLIT>
__device__ __forceinline__ void compute_chunk(
    const float (*As)[132], const float (*Bs)[132],
    float4 (&c)[4][4], int lane, int mw, int nw)
{
    const int gid = lane >> 2;   // 0..7
    const int tig = lane & 3;    // 0..3
#pragma unroll
    for (int ks = 0; ks < 16; ks += 8) {
        uint32_t ahi[4][4], alo[4][4];
        uint32_t bhi[4][2], blo[4][2];
#pragma unroll
        for (int f = 0; f < 4; f++) {
            const int r = mw + f * 16 + gid;
            float a0 = As[ks + tig][r];
            float a1 = As[ks + tig][r + 8];
            float a2 = As[ks + tig + 4][r];
            float a3 = As[ks + tig + 4][r + 8];
            ahi[f][0] = f2tf(a0); ahi[f][1] = f2tf(a1);
            ahi[f][2] = f2tf(a2); ahi[f][3] = f2tf(a3);
            if (SPLIT) {
                alo[f][0] = f2tf(a0 - __uint_as_float(ahi[f][0]));
                alo[f][1] = f2tf(a1 - __uint_as_float(ahi[f][1]));
                alo[f][2] = f2tf(a2 - __uint_as_float(ahi[f][2]));
                alo[f][3] = f2tf(a3 - __uint_as_float(ahi[f][3]));
            }
        }
#pragma unroll
        for (int g = 0; g < 4; g++) {
            const int n0 = nw + g * 8 + gid;
            float b0 = Bs[ks + tig][n0];
            float b1 = Bs[ks + tig + 4][n0];
            bhi[g][0] = f2tf(b0); bhi[g][1] = f2tf(b1);
            if (SPLIT) {
                blo[g][0] = f2tf(b0 - __uint_as_float(bhi[g][0]));
                blo[g][1] = f2tf(b1 - __uint_as_float(bhi[g][1]));
            }
        }
#pragma unroll
        for (int f = 0; f < 4; f++)
#pragma unroll
            for (int g = 0; g < 4; g++) {
                if (SPLIT) {
                    mma8(c[f][g], ahi[f], blo[g]);
                    mma8(c[f][g], alo[f], bhi[g]);
                }
                mma8(c[f][g], ahi[f], bhi[g]);
            }
    }
}

// ---------------------------------------------------------------------------
// K1a: f,g projection (rows 0..127 of Y) = [Wq;Wk] @ x.  SPLIT tf32.
// A needs k-transpose on smem store (W rows are k-contiguous). B (x) direct.
// ---------------------------------------------------------------------------
__global__ __launch_bounds__(256) void qkv_fg_gemm(
    const float* __restrict__ x,
    const float* __restrict__ Wq,
    const float* __restrict__ Wk)
{
    __shared__ float As[2][16][132];
    __shared__ float Bs[2][16][132];

    const int b = blockIdx.z;
    const int col0 = blockIdx.x * 128;
    const float* xb = x + (size_t)b * CC * NN;

    const int tid = threadIdx.x, lane = tid & 31, warp = tid >> 5;
    const int mw = (warp >> 2) * 64, nw = (warp & 3) * 32;

    // A: two (row, kquad) assignments; am0 in 0..63, second row = am0+64
    const int am0 = tid >> 2;
    const int ak  = (tid & 3) * 4;
    const float* arow0 = Wq + (size_t)am0 * CC;
    const float* arow1 = Wk + (size_t)am0 * CC;
    // B: krow bk0 in 0..7, second = +8
    const int bk0 = tid >> 5;
    const int bn  = (tid & 31) * 4;

    float4 c[4][4];
#pragma unroll
    for (int f = 0; f < 4; f++)
#pragma unroll
        for (int g = 0; g < 4; g++) c[f][g] = make_float4(0, 0, 0, 0);

    { // stage 0
        float4 a0 = *(const float4*)(arow0 + ak);
        float4 a1 = *(const float4*)(arow1 + ak);
        As[0][ak + 0][am0] = a0.x; As[0][ak + 1][am0] = a0.y;
        As[0][ak + 2][am0] = a0.z; As[0][ak + 3][am0] = a0.w;
        As[0][ak + 0][am0 + 64] = a1.x; As[0][ak + 1][am0 + 64] = a1.y;
        As[0][ak + 2][am0 + 64] = a1.z; As[0][ak + 3][am0 + 64] = a1.w;
        *(float4*)&Bs[0][bk0][bn]     = *(const float4*)(xb + (size_t)bk0 * NN + col0 + bn);
        *(float4*)&Bs[0][bk0 + 8][bn] = *(const float4*)(xb + (size_t)(bk0 + 8) * NN + col0 + bn);
    }
    __syncthreads();

    const int NS = CC / 16;
    for (int s = 0; s < NS; s++) {
        const int buf = s & 1;
        float4 pa0, pa1, pb0, pb1;
        if (s + 1 < NS) {
            const int kc = (s + 1) * 16;
            pa0 = *(const float4*)(arow0 + kc + ak);
            pa1 = *(const float4*)(arow1 + kc + ak);
            pb0 = *(const float4*)(xb + (size_t)(kc + bk0) * NN + col0 + bn);
            pb1 = *(const float4*)(xb + (size_t)(kc + bk0 + 8) * NN + col0 + bn);
        }
        compute_chunk<true>(As[buf], Bs[buf], c, lane, mw, nw);
        if (s + 1 < NS) {
            const int nb = buf ^ 1;
            As[nb][ak + 0][am0] = pa0.x; As[nb][ak + 1][am0] = pa0.y;
            As[nb][ak + 2][am0] = pa0.z; As[nb][ak + 3][am0] = pa0.w;
            As[nb][ak + 0][am0 + 64] = pa1.x; As[nb][ak + 1][am0 + 64] = pa1.y;
            As[nb][ak + 2][am0 + 64] = pa1.z; As[nb][ak + 3][am0 + 64] = pa1.w;
            *(float4*)&Bs[nb][bk0][bn] = pb0;
            *(float4*)&Bs[nb][bk0 + 8][bn] = pb1;
        }
        __syncthreads();
    }

    float* yb = d_Y + (size_t)b * RTOT * NN;
    const int gid = lane >> 2, tig = lane & 3;
#pragma unroll
    for (int f = 0; f < 4; f++) {
        const int r = mw + f * 16 + gid;
#pragma unroll
        for (int g = 0; g < 4; g++) {
            const int col = col0 + nw + g * 8 + 2 * tig;
            *(float2*)(yb + (size_t)r * NN + col)       = make_float2(c[f][g].x, c[f][g].y);
            *(float2*)(yb + (size_t)(r + 8) * NN + col) = make_float2(c[f][g].z, c[f][g].w);
        }
    }
}

// ---------------------------------------------------------------------------
// K1b: h projection (rows 128..639 of Y) = Wv @ x.  Single tf32.
// ---------------------------------------------------------------------------
__global__ __launch_bounds__(256) void qkv_h_gemm(
    const float* __restrict__ x,
    const float* __restrict__ Wv)
{
    __shared__ float As[2][16][132];
    __shared__ float Bs[2][16][132];

    const int b = blockIdx.z;
    const int row0 = blockIdx.y * 128;       // within Wv (0..511)
    const int col0 = blockIdx.x * 128;
    const float* xb = x + (size_t)b * CC * NN;

    const int tid = threadIdx.x, lane = tid & 31, warp = tid >> 5;
    const int mw = (warp >> 2) * 64, nw = (warp & 3) * 32;

    const int am0 = tid >> 2;
    const int ak  = (tid & 3) * 4;
    const float* arow0 = Wv + (size_t)(row0 + am0) * CC;
    const float* arow1 = Wv + (size_t)(row0 + am0 + 64) * CC;
    const int bk0 = tid >> 5;
    const int bn  = (tid & 31) * 4;

    float4 c[4][4];
#pragma unroll
    for (int f = 0; f < 4; f++)
#pragma unroll
        for (int g = 0; g < 4; g++) c[f][g] = make_float4(0, 0, 0, 0);

    {
        float4 a0 = *(const float4*)(arow0 + ak);
        float4 a1 = *(const float4*)(arow1 + ak);
        As[0][ak + 0][am0] = a0.x; As[0][ak + 1][am0] = a0.y;
        As[0][ak + 2][am0] = a0.z; As[0][ak + 3][am0] = a0.w;
        As[0][ak + 0][am0 + 64] = a1.x; As[0][ak + 1][am0 + 64] = a1.y;
        As[0][ak + 2][am0 + 64] = a1.z; As[0][ak + 3][am0 + 64] = a1.w;
        *(float4*)&Bs[0][bk0][bn]     = *(const float4*)(xb + (size_t)bk0 * NN + col0 + bn);
        *(float4*)&Bs[0][bk0 + 8][bn] = *(const float4*)(xb + (size_t)(bk0 + 8) * NN + col0 + bn);
    }
    __syncthreads();

    const int NS = CC / 16;
    for (int s = 0; s < NS; s++) {
        const int buf = s & 1;
        float4 pa0, pa1, pb0, pb1;
        if (s + 1 < NS) {
            const int kc = (s + 1) * 16;
            pa0 = *(const float4*)(arow0 + kc + ak);
            pa1 = *(const float4*)(arow1 + kc + ak);
            pb0 = *(const float4*)(xb + (size_t)(kc + bk0) * NN + col0 + bn);
            pb1 = *(const float4*)(xb + (size_t)(kc + bk0 + 8) * NN + col0 + bn);
        }
        compute_chunk<false>(As[buf], Bs[buf], c, lane, mw, nw);
        if (s + 1 < NS) {
            const int nb = buf ^ 1;
            As[nb][ak + 0][am0] = pa0.x; As[nb][ak + 1][am0] = pa0.y;
            As[nb][ak + 2][am0] = pa0.z; As[nb][ak + 3][am0] = pa0.w;
            As[nb][ak + 0][am0 + 64] = pa1.x; As[nb][ak + 1][am0 + 64] = pa1.y;
            As[nb][ak + 2][am0 + 64] = pa1.z; As[nb][ak + 3][am0 + 64] = pa1.w;
            *(float4*)&Bs[nb][bk0][bn] = pb0;
            *(float4*)&Bs[nb][bk0 + 8][bn] = pb1;
        }
        __syncthreads();
    }

    float* yb = d_Y + (size_t)b * RTOT * NN + (size_t)(2 * CQ + row0) * NN;
    const int gid = lane >> 2, tig = lane & 3;
#pragma unroll
    for (int f = 0; f < 4; f++) {
        const int r = mw + f * 16 + gid;
#pragma unroll
        for (int g = 0; g < 4; g++) {
            const int col = col0 + nw + g * 8 + 2 * tig;
            *(float2*)(yb + (size_t)r * NN + col)       = make_float2(c[f][g].x, c[f][g].y);
            *(float2*)(yb + (size_t)(r + 8) * NN + col) = make_float2(c[f][g].z, c[f][g].w);
        }
    }
}

// ---------------------------------------------------------------------------
// K2: scores[i][j] = leaky( sum_q F[q][i] * G[q][j] ), K=64.  SPLIT tf32.
// Both operands k-major -> direct smem copies.
// ---------------------------------------------------------------------------
__global__ __launch_bounds__(256) void scores_gemm_t()
{
    __shared__ float As[2][16][132];
    __shared__ float Bs[2][16][132];

    const int b  = blockIdx.z;
    const int i0 = blockIdx.y * 128;
    const int j0 = blockIdx.x * 128;
    const float* F = d_Y + (size_t)b * RTOT * NN;
    const float* G = F + (size_t)CQ * NN;

    const int tid = threadIdx.x, lane = tid & 31, warp = tid >> 5;
    const int mw = (warp >> 2) * 64, nw = (warp & 3) * 32;
    const int bk0 = tid >> 5;
    const int bn  = (tid & 31) * 4;

    float4 c[4][4];
#pragma unroll
    for (int f = 0; f < 4; f++)
#pragma unroll
        for (int g = 0; g < 4; g++) c[f][g] = make_float4(0, 0, 0, 0);

    {
        *(float4*)&As[0][bk0][bn]     = *(const float4*)(F + (size_t)bk0 * NN + i0 + bn);
        *(float4*)&As[0][bk0 + 8][bn] = *(const float4*)(F + (size_t)(bk0 + 8) * NN + i0 + bn);
        *(float4*)&Bs[0][bk0][bn]     = *(const float4*)(G + (size_t)bk0 * NN + j0 + bn);
        *(float4*)&Bs[0][bk0 + 8][bn] = *(const float4*)(G + (size_t)(bk0 + 8) * NN + j0 + bn);
    }
    __syncthreads();

    const int NS = CQ / 16;  // 4
    for (int s = 0; s < NS; s++) {
        const int buf = s & 1;
        float4 pa0, pa1, pb0, pb1;
        if (s + 1 < NS) {
            const int kc = (s + 1) * 16;
            pa0 = *(const float4*)(F + (size_t)(kc + bk0) * NN + i0 + bn);
            pa1 = *(const float4*)(F + (size_t)(kc + bk0 + 8) * NN + i0 + bn);
            pb0 = *(const float4*)(G + (size_t)(kc + bk0) * NN + j0 + bn);
            pb1 = *(const float4*)(G + (size_t)(kc + bk0 + 8) * NN + j0 + bn);
        }
        compute_chunk<true>(As[buf], Bs[buf], c, lane, mw, nw);
        if (s + 1 < NS) {
            const int nb = buf ^ 1;
            *(float4*)&As[nb][bk0][bn] = pa0;
            *(float4*)&As[nb][bk0 + 8][bn] = pa1;
            *(float4*)&Bs[nb][bk0][bn] = pb0;
            *(float4*)&Bs[nb][bk0 + 8][bn] = pb1;
        }
        __syncthreads();
    }

    float* S = d_scores + (size_t)b * NN * NN;
    const int gid = lane >> 2, tig = lane & 3;
#pragma unroll
    for (int f = 0; f < 4; f++) {
        const int r = i0 + mw + f * 16 + gid;
#pragma unroll
        for (int g = 0; g < 4; g++) {
            const int col = j0 + nw + g * 8 + 2 * tig;
            float s0 = c[f][g].x, s1 = c[f][g].y, s2 = c[f][g].z, s3 = c[f][g].w;
            s0 = s0 >= 0.0f ? s0 : 0.2f * s0;
            s1 = s1 >= 0.0f ? s1 : 0.2f * s1;
            s2 = s2 >= 0.0f ? s2 : 0.2f * s2;
            s3 = s3 >= 0.0f ? s3 : 0.2f * s3;
            *(float2*)(S + (size_t)r * NN + col)       = make_float2(s0, s1);
            *(float2*)(S + (size_t)(r + 8) * NN + col) = make_float2(s2, s3);
        }
    }
}

// ---------------------------------------------------------------------------
// K3: column softmax (over i) + mask renorm, in place. (unchanged, passing)
// ---------------------------------------------------------------------------
__global__ __launch_bounds__(256) void softmax_kernel(const float* __restrict__ mask)
{
    const int b = blockIdx.y;
    const int j = blockIdx.x * 256 + threadIdx.x;
    float* S = d_scores + (size_t)b * NN * NN;
    const float* mb = mask + (size_t)b * NN;

    float m0 = -1e30f, m1 = -1e30f, m2 = -1e30f, m3 = -1e30f;
    for (int i = 0; i < NN; i += 4) {
        m0 = fmaxf(m0, S[(size_t)(i + 0) * NN + j]);
        m1 = fmaxf(m1, S[(size_t)(i + 1) * NN + j]);
        m2 = fmaxf(m2, S[(size_t)(i + 2) * NN + j]);
        m3 = fmaxf(m3, S[(size_t)(i + 3) * NN + j]);
    }
    const float mx = fmaxf(fmaxf(m0, m1), fmaxf(m2, m3));

    float z0 = 0, z1 = 0, z2 = 0, z3 = 0;
    float s0 = 0, s1 = 0, s2 = 0, s3 = 0;
    for (int i = 0; i < NN; i += 4) {
        float e0 = __expf(S[(size_t)(i + 0) * NN + j] - mx);
        float e1 = __expf(S[(size_t)(i + 1) * NN + j] - mx);
        float e2 = __expf(S[(size_t)(i + 2) * NN + j] - mx);
        float e3 = __expf(S[(size_t)(i + 3) * NN + j] - mx);
        z0 += e0; z1 += e1; z2 += e2; z3 += e3;
        s0 += __ldg(&mb[i + 0]) * e0;
        s1 += __ldg(&mb[i + 1]) * e1;
        s2 += __ldg(&mb[i + 2]) * e2;
        s3 += __ldg(&mb[i + 3]) * e3;
    }
    const float Z  = (z0 + z1) + (z2 + z3);
    const float Sm = (s0 + s1) + (s2 + s3);
    const float inv = 1.0f / (Sm + 1e-6f * Z);

    for (int i = 0; i < NN; i++) {
        float e = __expf(S[(size_t)i * NN + j] - mx);
        S[(size_t)i * NN + j] = __ldg(&mb[i]) * e * inv;
    }
}

// ---------------------------------------------------------------------------
// K4: out[c][m] = gamma*(sum_n h[c][n]*beta[n][m])*mask[m] + x[c][m]. Single tf32.
// A = h (k-contiguous -> transpose store). B = beta (direct).
// ---------------------------------------------------------------------------
__global__ __launch_bounds__(256) void out_gemm_t(
    const float* __restrict__ x,
    const float* __restrict__ mask,
    const float* __restrict__ gamma,
    float* __restrict__ out)
{
    __shared__ float As[2][16][132];
    __shared__ float Bs[2][16][132];

    const int b  = blockIdx.z;
    const int c0 = blockIdx.y * 128;
    const int m0 = blockIdx.x * 128;
    const float* h  = d_Y + (size_t)b * RTOT * NN + (size_t)(2 * CQ) * NN;
    const float* Bt = d_scores + (size_t)b * NN * NN;

    const int tid = threadIdx.x, lane = tid & 31, warp = tid >> 5;
    const int mw = (warp >> 2) * 64, nw = (warp & 3) * 32;

    const int am0 = tid >> 2;
    const int ak  = (tid & 3) * 4;
    const float* arow0 = h + (size_t)(c0 + am0) * NN;
    const float* arow1 = h + (size_t)(c0 + am0 + 64) * NN;
    const int bk0 = tid >> 5;
    const int bn  = (tid & 31) * 4;

    float4 c[4][4];
#pragma unroll
    for (int f = 0; f < 4; f++)
#pragma unroll
        for (int g = 0; g < 4; g++) c[f][g] = make_float4(0, 0, 0, 0);

    {
        float4 a0 = *(const float4*)(arow0 + ak);
        float4 a1 = *(const float4*)(arow1 + ak);
        As[0][ak + 0][am0] = a0.x; As[0][ak + 1][am0] = a0.y;
        As[0][ak + 2][am0] = a0.z; As[0][ak + 3][am0] = a0.w;
        As[0][ak + 0][am0 + 64] = a1.x; As[0][ak + 1][am0 + 64] = a1.y;
        As[0][ak + 2][am0 + 64] = a1.z; As[0][ak + 3][am0 + 64] = a1.w;
        *(float4*)&Bs[0][bk0][bn]     = *(const float4*)(Bt + (size_t)bk0 * NN + m0 + bn);
        *(float4*)&Bs[0][bk0 + 8][bn] = *(const float4*)(Bt + (size_t)(bk0 + 8) * NN + m0 + bn);
    }
    __syncthreads();

    const int NS = NN / 16;  // 64
    for (int s = 0; s < NS; s++) {
        const int buf = s & 1;
        float4 pa0, pa1, pb0, pb1;
        if (s + 1 < NS) {
            const int kc = (s + 1) * 16;
            pa0 = *(const float4*)(arow0 + kc + ak);
            pa1 = *(const float4*)(arow1 + kc + ak);
            pb0 = *(const float4*)(Bt + (size_t)(kc + bk0) * NN + m0 + bn);
            pb1 = *(const float4*)(Bt + (size_t)(kc + bk0 + 8) * NN + m0 + bn);
        }
        compute_chunk<false>(As[buf], Bs[buf], c, lane, mw, nw);
        if (s + 1 < NS) {
            const int nb = buf ^ 1;
            As[nb][ak + 0][am0] = pa0.x; As[nb][ak + 1][am0] = pa0.y;
            As[nb][ak + 2][am0] = pa0.z; As[nb][ak + 3][am0] = pa0.w;
            As[nb][ak + 0][am0 + 64] = pa1.x; As[nb][ak + 1][am0 + 64] = pa1.y;
            As[nb][ak + 2][am0 + 64] = pa1.z; As[nb][ak + 3][am0 + 64] = pa1.w;
            *(float4*)&Bs[nb][bk0][bn] = pb0;
            *(float4*)&Bs[nb][bk0 + 8][bn] = pb1;
        }
        __syncthreads();
    }

    const float g0 = gamma[0];
    const float* xb = x + (size_t)b * CC * NN;
    float* ob = out + (size_t)b * CC * NN;
    const float* mb = mask + (size_t)b * NN;
    const int gid = lane >> 2, tig = lane & 3;

#pragma unroll
    for (int f = 0; f < 4; f++) {
        const int r = c0 + mw + f * 16 + gid;
#pragma unroll
        for (int g = 0; g < 4; g++) {
            const int col = m0 + nw + g * 8 + 2 * tig;
            float2 mv = *(const float2*)(mb + col);
            float2 x0 = *(const float2*)(xb + (size_t)r * NN + col);
            float2 x1 = *(const float2*)(xb + (size_t)(r + 8) * NN + col);
            float2 o0, o1;
            o0.x = g0 * c[f][g].x * mv.x + x0.x;
            o0.y = g0 * c[f][g].y * mv.y + x0.y;
            o1.x = g0 * c[f][g].z * mv.x + x1.x;
            o1.y = g0 * c[f][g].w * mv.y + x1.y;
            *(float2*)(ob + (size_t)r * NN + col)       = o0;
            *(float2*)(ob + (size_t)(r + 8) * NN + col) = o1;
        }
    }
}

// ---------------------------------------------------------------------------
extern "C" void kernel_launch(void* const* d_in, const int* in_sizes, int n_in,
                              void* d_out, int out_size)
{
    const float* x     = (const float*)d_in[0];
    const float* mask  = (const float*)d_in[1];
    const float* Wq    = (const float*)d_in[2];
    const float* Wk    = (const float*)d_in[3];
    const float* Wv    = (const float*)d_in[4];
    const float* gamma = (const float*)d_in[5];
    float* out = (float*)d_out;

    qkv_fg_gemm<<<dim3(NN / 128, 1, BB), 256>>>(x, Wq, Wk);
    qkv_h_gemm<<<dim3(NN / 128, 4, BB), 256>>>(x, Wv);
    scores_gemm_t<<<dim3(NN / 128, NN / 128, BB), 256>>>();
    softmax_kernel<<<dim3(NN / 256, BB), 256>>>(mask);
    out_gemm_t<<<dim3(NN / 128, CC / 128, BB), 256>>>(x, mask, gamma, out);
}

// round 5
// speedup vs baseline: 1.9425x; 1.0254x over previous
#include <cuda_runtime.h>
#include <cstdint>

// Problem dims (fixed by the dataset)
#define BB   64
#define CC   512
#define NN   1024
#define CQ   64
#define RTOT 640   // Wq(64) + Wk(64) + Wv(512) rows

// Scratch
__device__ float d_Y[(size_t)BB * RTOT * NN];        // f/g rows 0..127, h' rows 128..639
__device__ float d_scores[(size_t)BB * NN * NN];     // E = exp(leaky(scores))
__device__ float d_partZ[(size_t)BB * 8 * NN];       // per-i-tile column partial sums
__device__ float d_partSm[(size_t)BB * 8 * NN];
__device__ float d_colZ[(size_t)BB * NN];
__device__ float d_colSm[(size_t)BB * NN];

// ---------------------------------------------------------------------------
// tf32 helpers
// ---------------------------------------------------------------------------
__device__ __forceinline__ uint32_t f2tf(float f) {
    uint32_t u;
    asm("cvt.rna.tf32.f32 %0, %1;" : "=r"(u) : "f"(f));
    return u;
}

__device__ __forceinline__ void mma8(float4& d, const uint32_t a[4], const uint32_t b[2]) {
    asm volatile(
        "mma.sync.aligned.m16n8k8.row.col.f32.tf32.tf32.f32 "
        "{%0,%1,%2,%3}, {%4,%5,%6,%7}, {%8,%9}, {%0,%1,%2,%3};"
        : "+f"(d.x), "+f"(d.y), "+f"(d.z), "+f"(d.w)
        : "r"(a[0]), "r"(a[1]), "r"(a[2]), "r"(a[3]), "r"(b[0]), "r"(b[1]));
}

// ---------------------------------------------------------------------------
// Split (3xTF32) chunk: operands in fp32 smem, converted on the fly.
// ---------------------------------------------------------------------------
__device__ __forceinline__ void compute_chunk_split(
    const float (*As)[132], const float (*Bs)[132],
    float4 (&c)[4][4], int lane, int mw, int nw)
{
    const int gid = lane >> 2;
    const int tig = lane & 3;
#pragma unroll
    for (int ks = 0; ks < 16; ks += 8) {
        uint32_t ahi[4][4], alo[4][4];
        uint32_t bhi[4][2], blo[4][2];
#pragma unroll
        for (int f = 0; f < 4; f++) {
            const int r = mw + f * 16 + gid;
            float a0 = As[ks + tig][r];
            float a1 = As[ks + tig][r + 8];
            float a2 = As[ks + tig + 4][r];
            float a3 = As[ks + tig + 4][r + 8];
            ahi[f][0] = f2tf(a0); ahi[f][1] = f2tf(a1);
            ahi[f][2] = f2tf(a2); ahi[f][3] = f2tf(a3);
            alo[f][0] = f2tf(a0 - __uint_as_float(ahi[f][0]));
            alo[f][1] = f2tf(a1 - __uint_as_float(ahi[f][1]));
            alo[f][2] = f2tf(a2 - __uint_as_float(ahi[f][2]));
            alo[f][3] = f2tf(a3 - __uint_as_float(ahi[f][3]));
        }
#pragma unroll
        for (int g = 0; g < 4; g++) {
            const int n0 = nw + g * 8 + gid;
            float b0 = Bs[ks + tig][n0];
            float b1 = Bs[ks + tig + 4][n0];
            bhi[g][0] = f2tf(b0); bhi[g][1] = f2tf(b1);
            blo[g][0] = f2tf(b0 - __uint_as_float(bhi[g][0]));
            blo[g][1] = f2tf(b1 - __uint_as_float(bhi[g][1]));
        }
#pragma unroll
        for (int f = 0; f < 4; f++)
#pragma unroll
            for (int g = 0; g < 4; g++) {
                mma8(c[f][g], ahi[f], blo[g]);
                mma8(c[f][g], alo[f], bhi[g]);
                mma8(c[f][g], ahi[f], bhi[g]);
            }
    }
}

// ---------------------------------------------------------------------------
// Pre-converted chunk: operands already tf32 bits in smem -> pure LDS + MMA.
// ---------------------------------------------------------------------------
__device__ __forceinline__ void compute_chunk_u(
    const uint32_t (*As)[132], const uint32_t (*Bs)[132],
    float4 (&c)[4][4], int lane, int mw, int nw)
{
    const int gid = lane >> 2;
    const int tig = lane & 3;
#pragma unroll
    for (int ks = 0; ks < 16; ks += 8) {
        uint32_t a[4][4], bfr[4][2];
#pragma unroll
        for (int f = 0; f < 4; f++) {
            const int r = mw + f * 16 + gid;
            a[f][0] = As[ks + tig][r];
            a[f][1] = As[ks + tig][r + 8];
            a[f][2] = As[ks + tig + 4][r];
            a[f][3] = As[ks + tig + 4][r + 8];
        }
#pragma unroll
        for (int g = 0; g < 4; g++) {
            const int n0 = nw + g * 8 + gid;
            bfr[g][0] = Bs[ks + tig][n0];
            bfr[g][1] = Bs[ks + tig + 4][n0];
        }
#pragma unroll
        for (int f = 0; f < 4; f++)
#pragma unroll
            for (int g = 0; g < 4; g++)
                mma8(c[f][g], a[f], bfr[g]);
    }
}

// ---------------------------------------------------------------------------
// K1a: f,g projection (rows 0..127 of Y) = [Wq;Wk] @ x.  SPLIT tf32.
// ---------------------------------------------------------------------------
__global__ __launch_bounds__(256) void qkv_fg_gemm(
    const float* __restrict__ x,
    const float* __restrict__ Wq,
    const float* __restrict__ Wk)
{
    __shared__ float As[2][16][132];
    __shared__ float Bs[2][16][132];

    const int b = blockIdx.z;
    const int col0 = blockIdx.x * 128;
    const float* xb = x + (size_t)b * CC * NN;

    const int tid = threadIdx.x, lane = tid & 31, warp = tid >> 5;
    const int mw = (warp >> 2) * 64, nw = (warp & 3) * 32;

    const int am0 = tid >> 2;
    const int ak  = (tid & 3) * 4;
    const float* arow0 = Wq + (size_t)am0 * CC;
    const float* arow1 = Wk + (size_t)am0 * CC;
    const int bk0 = tid >> 5;
    const int bn  = (tid & 31) * 4;

    float4 c[4][4];
#pragma unroll
    for (int f = 0; f < 4; f++)
#pragma unroll
        for (int g = 0; g < 4; g++) c[f][g] = make_float4(0, 0, 0, 0);

    {
        float4 a0 = *(const float4*)(arow0 + ak);
        float4 a1 = *(const float4*)(arow1 + ak);
        As[0][ak + 0][am0] = a0.x; As[0][ak + 1][am0] = a0.y;
        As[0][ak + 2][am0] = a0.z; As[0][ak + 3][am0] = a0.w;
        As[0][ak + 0][am0 + 64] = a1.x; As[0][ak + 1][am0 + 64] = a1.y;
        As[0][ak + 2][am0 + 64] = a1.z; As[0][ak + 3][am0 + 64] = a1.w;
        *(float4*)&Bs[0][bk0][bn]     = *(const float4*)(xb + (size_t)bk0 * NN + col0 + bn);
        *(float4*)&Bs[0][bk0 + 8][bn] = *(const float4*)(xb + (size_t)(bk0 + 8) * NN + col0 + bn);
    }
    __syncthreads();

    const int NS = CC / 16;
    for (int s = 0; s < NS; s++) {
        const int buf = s & 1;
        float4 pa0, pa1, pb0, pb1;
        if (s + 1 < NS) {
            const int kc = (s + 1) * 16;
            pa0 = *(const float4*)(arow0 + kc + ak);
            pa1 = *(const float4*)(arow1 + kc + ak);
            pb0 = *(const float4*)(xb + (size_t)(kc + bk0) * NN + col0 + bn);
            pb1 = *(const float4*)(xb + (size_t)(kc + bk0 + 8) * NN + col0 + bn);
        }
        compute_chunk_split(As[buf], Bs[buf], c, lane, mw, nw);
        if (s + 1 < NS) {
            const int nb = buf ^ 1;
            As[nb][ak + 0][am0] = pa0.x; As[nb][ak + 1][am0] = pa0.y;
            As[nb][ak + 2][am0] = pa0.z; As[nb][ak + 3][am0] = pa0.w;
            As[nb][ak + 0][am0 + 64] = pa1.x; As[nb][ak + 1][am0 + 64] = pa1.y;
            As[nb][ak + 2][am0 + 64] = pa1.z; As[nb][ak + 3][am0 + 64] = pa1.w;
            *(float4*)&Bs[nb][bk0][bn] = pb0;
            *(float4*)&Bs[nb][bk0 + 8][bn] = pb1;
        }
        __syncthreads();
    }

    float* yb = d_Y + (size_t)b * RTOT * NN;
    const int gid = lane >> 2, tig = lane & 3;
#pragma unroll
    for (int f = 0; f < 4; f++) {
        const int r = mw + f * 16 + gid;
#pragma unroll
        for (int g = 0; g < 4; g++) {
            const int col = col0 + nw + g * 8 + 2 * tig;
            *(float2*)(yb + (size_t)r * NN + col)       = make_float2(c[f][g].x, c[f][g].y);
            *(float2*)(yb + (size_t)(r + 8) * NN + col) = make_float2(c[f][g].z, c[f][g].w);
        }
    }
}

// ---------------------------------------------------------------------------
// K1b: h' projection (rows 128..639 of Y) = (Wv @ x) * mask[col].
// Single tf32, pre-converted smem.
// ---------------------------------------------------------------------------
__global__ __launch_bounds__(256) void qkv_h_gemm(
    const float* __restrict__ x,
    const float* __restrict__ Wv,
    const float* __restrict__ mask)
{
    __shared__ uint32_t As[2][16][132];
    __shared__ uint32_t Bs[2][16][132];

    const int b = blockIdx.z;
    const int row0 = blockIdx.y * 128;
    const int col0 = blockIdx.x * 128;
    const float* xb = x + (size_t)b * CC * NN;

    const int tid = threadIdx.x, lane = tid & 31, warp = tid >> 5;
    const int mw = (warp >> 2) * 64, nw = (warp & 3) * 32;

    const int am0 = tid >> 2;
    const int ak  = (tid & 3) * 4;
    const float* arow0 = Wv + (size_t)(row0 + am0) * CC;
    const float* arow1 = Wv + (size_t)(row0 + am0 + 64) * CC;
    const int bk0 = tid >> 5;
    const int bn  = (tid & 31) * 4;

    float4 c[4][4];
#pragma unroll
    for (int f = 0; f < 4; f++)
#pragma unroll
        for (int g = 0; g < 4; g++) c[f][g] = make_float4(0, 0, 0, 0);

    {
        float4 a0 = *(const float4*)(arow0 + ak);
        float4 a1 = *(const float4*)(arow1 + ak);
        As[0][ak + 0][am0] = f2tf(a0.x); As[0][ak + 1][am0] = f2tf(a0.y);
        As[0][ak + 2][am0] = f2tf(a0.z); As[0][ak + 3][am0] = f2tf(a0.w);
        As[0][ak + 0][am0 + 64] = f2tf(a1.x); As[0][ak + 1][am0 + 64] = f2tf(a1.y);
        As[0][ak + 2][am0 + 64] = f2tf(a1.z); As[0][ak + 3][am0 + 64] = f2tf(a1.w);
        float4 b0 = *(const float4*)(xb + (size_t)bk0 * NN + col0 + bn);
        float4 b1 = *(const float4*)(xb + (size_t)(bk0 + 8) * NN + col0 + bn);
        Bs[0][bk0][bn + 0] = f2tf(b0.x); Bs[0][bk0][bn + 1] = f2tf(b0.y);
        Bs[0][bk0][bn + 2] = f2tf(b0.z); Bs[0][bk0][bn + 3] = f2tf(b0.w);
        Bs[0][bk0 + 8][bn + 0] = f2tf(b1.x); Bs[0][bk0 + 8][bn + 1] = f2tf(b1.y);
        Bs[0][bk0 + 8][bn + 2] = f2tf(b1.z); Bs[0][bk0 + 8][bn + 3] = f2tf(b1.w);
    }
    __syncthreads();

    const int NS = CC / 16;
    for (int s = 0; s < NS; s++) {
        const int buf = s & 1;
        float4 pa0, pa1, pb0, pb1;
        if (s + 1 < NS) {
            const int kc = (s + 1) * 16;
            pa0 = *(const float4*)(arow0 + kc + ak);
            pa1 = *(const float4*)(arow1 + kc + ak);
            pb0 = *(const float4*)(xb + (size_t)(kc + bk0) * NN + col0 + bn);
            pb1 = *(const float4*)(xb + (size_t)(kc + bk0 + 8) * NN + col0 + bn);
        }
        compute_chunk_u(As[buf], Bs[buf], c, lane, mw, nw);
        if (s + 1 < NS) {
            const int nb = buf ^ 1;
            As[nb][ak + 0][am0] = f2tf(pa0.x); As[nb][ak + 1][am0] = f2tf(pa0.y);
            As[nb][ak + 2][am0] = f2tf(pa0.z); As[nb][ak + 3][am0] = f2tf(pa0.w);
            As[nb][ak + 0][am0 + 64] = f2tf(pa1.x); As[nb][ak + 1][am0 + 64] = f2tf(pa1.y);
            As[nb][ak + 2][am0 + 64] = f2tf(pa1.z); As[nb][ak + 3][am0 + 64] = f2tf(pa1.w);
            Bs[nb][bk0][bn + 0] = f2tf(pb0.x); Bs[nb][bk0][bn + 1] = f2tf(pb0.y);
            Bs[nb][bk0][bn + 2] = f2tf(pb0.z); Bs[nb][bk0][bn + 3] = f2tf(pb0.w);
            Bs[nb][bk0 + 8][bn + 0] = f2tf(pb1.x); Bs[nb][bk0 + 8][bn + 1] = f2tf(pb1.y);
            Bs[nb][bk0 + 8][bn + 2] = f2tf(pb1.z); Bs[nb][bk0 + 8][bn + 3] = f2tf(pb1.w);
        }
        __syncthreads();
    }

    float* yb = d_Y + (size_t)b * RTOT * NN + (size_t)(2 * CQ + row0) * NN;
    const float* mb = mask + (size_t)b * NN;
    const int gid = lane >> 2, tig = lane & 3;
#pragma unroll
    for (int f = 0; f < 4; f++) {
        const int r = mw + f * 16 + gid;
#pragma unroll
        for (int g = 0; g < 4; g++) {
            const int col = col0 + nw + g * 8 + 2 * tig;
            float2 mv = *(const float2*)(mb + col);
            *(float2*)(yb + (size_t)r * NN + col) =
                make_float2(c[f][g].x * mv.x, c[f][g].y * mv.y);
            *(float2*)(yb + (size_t)(r + 8) * NN + col) =
                make_float2(c[f][g].z * mv.x, c[f][g].w * mv.y);
        }
    }
}

// ---------------------------------------------------------------------------
// K2: E[i][j] = exp(leaky(sum_q F[q][i]*G[q][j])), K=64, SPLIT tf32.
// Also emits per-block column partial sums of Z and mask*E (no atomics:
// each (b, i-tile) owns a unique partial slot).
// ---------------------------------------------------------------------------
__global__ __launch_bounds__(256) void scores_gemm_t(const float* __restrict__ mask)
{
    __shared__ float As[2][16][132];
    __shared__ float Bs[2][16][132];
    __shared__ float sZ[128];
    __shared__ float sSm[128];

    const int b  = blockIdx.z;
    const int it = blockIdx.y;
    const int i0 = it * 128;
    const int j0 = blockIdx.x * 128;
    const float* F = d_Y + (size_t)b * RTOT * NN;
    const float* G = F + (size_t)CQ * NN;

    const int tid = threadIdx.x, lane = tid & 31, warp = tid >> 5;
    const int mw = (warp >> 2) * 64, nw = (warp & 3) * 32;
    const int bk0 = tid >> 5;
    const int bn  = (tid & 31) * 4;

    if (tid < 128) { sZ[tid] = 0.0f; sSm[tid] = 0.0f; }

    float4 c[4][4];
#pragma unroll
    for (int f = 0; f < 4; f++)
#pragma unroll
        for (int g = 0; g < 4; g++) c[f][g] = make_float4(0, 0, 0, 0);

    {
        *(float4*)&As[0][bk0][bn]     = *(const float4*)(F + (size_t)bk0 * NN + i0 + bn);
        *(float4*)&As[0][bk0 + 8][bn] = *(const float4*)(F + (size_t)(bk0 + 8) * NN + i0 + bn);
        *(float4*)&Bs[0][bk0][bn]     = *(const float4*)(G + (size_t)bk0 * NN + j0 + bn);
        *(float4*)&Bs[0][bk0 + 8][bn] = *(const float4*)(G + (size_t)(bk0 + 8) * NN + j0 + bn);
    }
    __syncthreads();

    const int NS = CQ / 16;  // 4
    for (int s = 0; s < NS; s++) {
        const int buf = s & 1;
        float4 pa0, pa1, pb0, pb1;
        if (s + 1 < NS) {
            const int kc = (s + 1) * 16;
            pa0 = *(const float4*)(F + (size_t)(kc + bk0) * NN + i0 + bn);
            pa1 = *(const float4*)(F + (size_t)(kc + bk0 + 8) * NN + i0 + bn);
            pb0 = *(const float4*)(G + (size_t)(kc + bk0) * NN + j0 + bn);
            pb1 = *(const float4*)(G + (size_t)(kc + bk0 + 8) * NN + j0 + bn);
        }
        compute_chunk_split(As[buf], Bs[buf], c, lane, mw, nw);
        if (s + 1 < NS) {
            const int nb = buf ^ 1;
            *(float4*)&As[nb][bk0][bn] = pa0;
            *(float4*)&As[nb][bk0 + 8][bn] = pa1;
            *(float4*)&Bs[nb][bk0][bn] = pb0;
            *(float4*)&Bs[nb][bk0 + 8][bn] = pb1;
        }
        __syncthreads();
    }

    float* S = d_scores + (size_t)b * NN * NN;
    const float* mb = mask + (size_t)b * NN;
    const int gid = lane >> 2, tig = lane & 3;

    // mask values for this thread's rows
    float mrow[4][2];
#pragma unroll
    for (int f = 0; f < 4; f++) {
        const int r = i0 + mw + f * 16 + gid;
        mrow[f][0] = __ldg(&mb[r]);
        mrow[f][1] = __ldg(&mb[r + 8]);
    }

#pragma unroll
    for (int g = 0; g < 4; g++) {
        const int colL = nw + g * 8 + 2 * tig;   // tile-local column
        float z0 = 0, z1 = 0, sm0 = 0, sm1 = 0;
#pragma unroll
        for (int f = 0; f < 4; f++) {
            const int r = i0 + mw + f * 16 + gid;
            float s0 = c[f][g].x, s1 = c[f][g].y, s2 = c[f][g].z, s3 = c[f][g].w;
            s0 = s0 >= 0.0f ? s0 : 0.2f * s0;
            s1 = s1 >= 0.0f ? s1 : 0.2f * s1;
            s2 = s2 >= 0.0f ? s2 : 0.2f * s2;
            s3 = s3 >= 0.0f ? s3 : 0.2f * s3;
            float e0 = __expf(fminf(s0, 75.0f));
            float e1 = __expf(fminf(s1, 75.0f));
            float e2 = __expf(fminf(s2, 75.0f));
            float e3 = __expf(fminf(s3, 75.0f));
            *(float2*)(S + (size_t)r * NN + j0 + colL)       = make_float2(e0, e1);
            *(float2*)(S + (size_t)(r + 8) * NN + j0 + colL) = make_float2(e2, e3);
            z0 += e0 + e2;   z1 += e1 + e3;
            sm0 += mrow[f][0] * e0 + mrow[f][1] * e2;
            sm1 += mrow[f][0] * e1 + mrow[f][1] * e3;
        }
        atomicAdd(&sZ[colL], z0);       atomicAdd(&sZ[colL + 1], z1);
        atomicAdd(&sSm[colL], sm0);     atomicAdd(&sSm[colL + 1], sm1);
    }
    __syncthreads();
    if (tid < 128) {
        const size_t off = ((size_t)b * 8 + it) * NN + j0 + tid;
        d_partZ[off]  = sZ[tid];
        d_partSm[off] = sSm[tid];
    }
}

// ---------------------------------------------------------------------------
// K2b: fold 8 i-tile partials into column sums.
// ---------------------------------------------------------------------------
__global__ __launch_bounds__(256) void reduce_sums()
{
    const int b = blockIdx.y;
    const int j = blockIdx.x * 256 + threadIdx.x;
    float z = 0.0f, s = 0.0f;
#pragma unroll
    for (int t = 0; t < 8; t++) {
        const size_t off = ((size_t)b * 8 + t) * NN + j;
        z += d_partZ[off];
        s += d_partSm[off];
    }
    d_colZ[(size_t)b * NN + j]  = z;
    d_colSm[(size_t)b * NN + j] = s;
}

// ---------------------------------------------------------------------------
// K4: out[c][m] = gamma * (sum_n h'[c][n]*E[n][m]) * mask[m]/(Sm[m]+eps*Z[m]) + x[c][m]
// Single tf32, pre-converted smem.
// ---------------------------------------------------------------------------
__global__ __launch_bounds__(256) void out_gemm_t(
    const float* __restrict__ x,
    const float* __restrict__ mask,
    const float* __restrict__ gamma,
    float* __restrict__ out)
{
    __shared__ uint32_t As[2][16][132];
    __shared__ uint32_t Bs[2][16][132];

    const int b  = blockIdx.z;
    const int c0 = blockIdx.y * 128;
    const int m0 = blockIdx.x * 128;
    const float* h  = d_Y + (size_t)b * RTOT * NN + (size_t)(2 * CQ) * NN;
    const float* Bt = d_scores + (size_t)b * NN * NN;   // E

    const int tid = threadIdx.x, lane = tid & 31, warp = tid >> 5;
    const int mw = (warp >> 2) * 64, nw = (warp & 3) * 32;

    const int am0 = tid >> 2;
    const int ak  = (tid & 3) * 4;
    const float* arow0 = h + (size_t)(c0 + am0) * NN;
    const float* arow1 = h + (size_t)(c0 + am0 + 64) * NN;
    const int bk0 = tid >> 5;
    const int bn  = (tid & 31) * 4;

    float4 c[4][4];
#pragma unroll
    for (int f = 0; f < 4; f++)
#pragma unroll
        for (int g = 0; g < 4; g++) c[f][g] = make_float4(0, 0, 0, 0);

    {
        float4 a0 = *(const float4*)(arow0 + ak);
        float4 a1 = *(const float4*)(arow1 + ak);
        As[0][ak + 0][am0] = f2tf(a0.x); As[0][ak + 1][am0] = f2tf(a0.y);
        As[0][ak + 2][am0] = f2tf(a0.z); As[0][ak + 3][am0] = f2tf(a0.w);
        As[0][ak + 0][am0 + 64] = f2tf(a1.x); As[0][ak + 1][am0 + 64] = f2tf(a1.y);
        As[0][ak + 2][am0 + 64] = f2tf(a1.z); As[0][ak + 3][am0 + 64] = f2tf(a1.w);
        float4 b0 = *(const float4*)(Bt + (size_t)bk0 * NN + m0 + bn);
        float4 b1 = *(const float4*)(Bt + (size_t)(bk0 + 8) * NN + m0 + bn);
        Bs[0][bk0][bn + 0] = f2tf(b0.x); Bs[0][bk0][bn + 1] = f2tf(b0.y);
        Bs[0][bk0][bn + 2] = f2tf(b0.z); Bs[0][bk0][bn + 3] = f2tf(b0.w);
        Bs[0][bk0 + 8][bn + 0] = f2tf(b1.x); Bs[0][bk0 + 8][bn + 1] = f2tf(b1.y);
        Bs[0][bk0 + 8][bn + 2] = f2tf(b1.z); Bs[0][bk0 + 8][bn + 3] = f2tf(b1.w);
    }
    __syncthreads();

    const int NS = NN / 16;  // 64
    for (int s = 0; s < NS; s++) {
        const int buf = s & 1;
        float4 pa0, pa1, pb0, pb1;
        if (s + 1 < NS) {
            const int kc = (s + 1) * 16;
            pa0 = *(const float4*)(arow0 + kc + ak);
            pa1 = *(const float4*)(arow1 + kc + ak);
            pb0 = *(const float4*)(Bt + (size_t)(kc + bk0) * NN + m0 + bn);
            pb1 = *(const float4*)(Bt + (size_t)(kc + bk0 + 8) * NN + m0 + bn);
        }
        compute_chunk_u(As[buf], Bs[buf], c, lane, mw, nw);
        if (s + 1 < NS) {
            const int nb = buf ^ 1;
            As[nb][ak + 0][am0] = f2tf(pa0.x); As[nb][ak + 1][am0] = f2tf(pa0.y);
            As[nb][ak + 2][am0] = f2tf(pa0.z); As[nb][ak + 3][am0] = f2tf(pa0.w);
            As[nb][ak + 0][am0 + 64] = f2tf(pa1.x); As[nb][ak + 1][am0 + 64] = f2tf(pa1.y);
            As[nb][ak + 2][am0 + 64] = f2tf(pa1.z); As[nb][ak + 3][am0 + 64] = f2tf(pa1.w);
            Bs[nb][bk0][bn + 0] = f2tf(pb0.x); Bs[nb][bk0][bn + 1] = f2tf(pb0.y);
            Bs[nb][bk0][bn + 2] = f2tf(pb0.z); Bs[nb][bk0][bn + 3] = f2tf(pb0.w);
            Bs[nb][bk0 + 8][bn + 0] = f2tf(pb1.x); Bs[nb][bk0 + 8][bn + 1] = f2tf(pb1.y);
            Bs[nb][bk0 + 8][bn + 2] = f2tf(pb1.z); Bs[nb][bk0 + 8][bn + 3] = f2tf(pb1.w);
        }
        __syncthreads();
    }

    const float g0 = gamma[0];
    const float* xb = x + (size_t)b * CC * NN;
    float* ob = out + (size_t)b * CC * NN;
    const float* mb = mask + (size_t)b * NN;
    const float* zc = d_colZ + (size_t)b * NN;
    const float* sc = d_colSm + (size_t)b * NN;
    const int gid = lane >> 2, tig = lane & 3;

#pragma unroll
    for (int g = 0; g < 4; g++) {
        const int col = m0 + nw + g * 8 + 2 * tig;
        float2 mv = *(const float2*)(mb + col);
        float2 zv = *(const float2*)(zc + col);
        float2 sv = *(const float2*)(sc + col);
        const float w0 = g0 * mv.x / (sv.x + 1e-6f * zv.x);
        const float w1 = g0 * mv.y / (sv.y + 1e-6f * zv.y);
#pragma unroll
        for (int f = 0; f < 4; f++) {
            const int r = c0 + mw + f * 16 + gid;
            float2 x0 = *(const float2*)(xb + (size_t)r * NN + col);
            float2 x1 = *(const float2*)(xb + (size_t)(r + 8) * NN + col);
            float2 o0, o1;
            o0.x = c[f][g].x * w0 + x0.x;
            o0.y = c[f][g].y * w1 + x0.y;
            o1.x = c[f][g].z * w0 + x1.x;
            o1.y = c[f][g].w * w1 + x1.y;
            *(float2*)(ob + (size_t)r * NN + col)       = o0;
            *(float2*)(ob + (size_t)(r + 8) * NN + col) = o1;
        }
    }
}

// ---------------------------------------------------------------------------
extern "C" void kernel_launch(void* const* d_in, const int* in_sizes, int n_in,
                              void* d_out, int out_size)
{
    const float* x     = (const float*)d_in[0];
    const float* mask  = (const float*)d_in[1];
    const float* Wq    = (const float*)d_in[2];
    const float* Wk    = (const float*)d_in[3];
    const float* Wv    = (const float*)d_in[4];
    const float* gamma = (const float*)d_in[5];
    float* out = (float*)d_out;

    qkv_fg_gemm<<<dim3(NN / 128, 1, BB), 256>>>(x, Wq, Wk);
    qkv_h_gemm<<<dim3(NN / 128, 4, BB), 256>>>(x, Wv, mask);
    scores_gemm_t<<<dim3(NN / 128, NN / 128, BB), 256>>>(mask);
    reduce_sums<<<dim3(NN / 256, BB), 256>>>();
    out_gemm_t<<<dim3(NN / 128, CC / 128, BB), 256>>>(x, mask, gamma, out);
}

// round 6
// speedup vs baseline: 2.6047x; 1.3409x over previous
#include <cuda_runtime.h>
#include <cstdint>

// Problem dims (fixed by the dataset)
#define BB   64
#define CC   512
#define NN   1024
#define CQ   64
#define RTOT 640   // Wq(64) + Wk(64) + Wv(512) rows

// Scratch
__device__ float d_Y[(size_t)BB * RTOT * NN];        // f/g rows 0..127, h' rows 128..639
__device__ float d_scores[(size_t)BB * NN * NN];     // E = exp(leaky(scores)), tf32-rounded
__device__ float d_xr[(size_t)BB * CC * NN];         // x rounded to tf32 (rna)
__device__ float d_Wvr[(size_t)CC * CC];             // Wv rounded to tf32 (rna)
__device__ float d_partZ[(size_t)BB * 8 * NN];
__device__ float d_partSm[(size_t)BB * 8 * NN];
__device__ float d_colZ[(size_t)BB * NN];
__device__ float d_colSm[(size_t)BB * NN];

// ---------------------------------------------------------------------------
// helpers
// ---------------------------------------------------------------------------
__device__ __forceinline__ uint32_t f2tf(float f) {
    uint32_t u;
    asm("cvt.rna.tf32.f32 %0, %1;" : "=r"(u) : "f"(f));
    return u;
}

__device__ __forceinline__ void mma8(float4& d, const uint32_t a[4], const uint32_t b[2]) {
    asm volatile(
        "mma.sync.aligned.m16n8k8.row.col.f32.tf32.tf32.f32 "
        "{%0,%1,%2,%3}, {%4,%5,%6,%7}, {%8,%9}, {%0,%1,%2,%3};"
        : "+f"(d.x), "+f"(d.y), "+f"(d.z), "+f"(d.w)
        : "r"(a[0]), "r"(a[1]), "r"(a[2]), "r"(a[3]), "r"(b[0]), "r"(b[1]));
}

__device__ __forceinline__ void cp16(void* dst_smem, const void* src_gmem) {
    uint32_t d = (uint32_t)__cvta_generic_to_shared(dst_smem);
    asm volatile("cp.async.cg.shared.global [%0], [%1], 16;" :: "r"(d), "l"(src_gmem));
}
#define CP_COMMIT() asm volatile("cp.async.commit_group;")
#define CP_WAIT0()  asm volatile("cp.async.wait_group 0;")

// ---------------------------------------------------------------------------
// Inner compute variants over one 128x128x16 chunk.
// A m-major [128][20]: lane addr = 20*gid + tig (mod 32) -> conflict-free.
// A k-major [16][136] / B [16][136]: lane addr = 8*tig + gid -> conflict-free.
// Warp tile 64x32: 4 m-frags x 4 n-frags.
// ---------------------------------------------------------------------------
__device__ __forceinline__ void compute_raw(
    const float (*As)[20], const float (*Bs)[136],
    float4 (&c)[4][4], int gid, int tig, int mw, int nw)
{
#pragma unroll
    for (int ks = 0; ks < 16; ks += 8) {
        uint32_t a[4][4], bfr[4][2];
#pragma unroll
        for (int f = 0; f < 4; f++) {
            const int r = mw + f * 16 + gid;
            a[f][0] = __float_as_uint(As[r][ks + tig]);
            a[f][1] = __float_as_uint(As[r + 8][ks + tig]);
            a[f][2] = __float_as_uint(As[r][ks + tig + 4]);
            a[f][3] = __float_as_uint(As[r + 8][ks + tig + 4]);
        }
#pragma unroll
        for (int g = 0; g < 4; g++) {
            const int n0 = nw + g * 8 + gid;
            bfr[g][0] = __float_as_uint(Bs[ks + tig][n0]);
            bfr[g][1] = __float_as_uint(Bs[ks + tig + 4][n0]);
        }
#pragma unroll
        for (int f = 0; f < 4; f++)
#pragma unroll
            for (int g = 0; g < 4; g++)
                mma8(c[f][g], a[f], bfr[g]);
    }
}

__device__ __forceinline__ void compute_split_mA(
    const float (*As)[20], const float (*Bs)[136],
    float4 (&c)[4][4], int gid, int tig, int mw, int nw)
{
#pragma unroll
    for (int ks = 0; ks < 16; ks += 8) {
        uint32_t ahi[4][4], alo[4][4];
        uint32_t bhi[4][2], blo[4][2];
#pragma unroll
        for (int f = 0; f < 4; f++) {
            const int r = mw + f * 16 + gid;
            float a0 = As[r][ks + tig];
            float a1 = As[r + 8][ks + tig];
            float a2 = As[r][ks + tig + 4];
            float a3 = As[r + 8][ks + tig + 4];
            ahi[f][0] = f2tf(a0); ahi[f][1] = f2tf(a1);
            ahi[f][2] = f2tf(a2); ahi[f][3] = f2tf(a3);
            alo[f][0] = f2tf(a0 - __uint_as_float(ahi[f][0]));
            alo[f][1] = f2tf(a1 - __uint_as_float(ahi[f][1]));
            alo[f][2] = f2tf(a2 - __uint_as_float(ahi[f][2]));
            alo[f][3] = f2tf(a3 - __uint_as_float(ahi[f][3]));
        }
#pragma unroll
        for (int g = 0; g < 4; g++) {
            const int n0 = nw + g * 8 + gid;
            float b0 = Bs[ks + tig][n0];
            float b1 = Bs[ks + tig + 4][n0];
            bhi[g][0] = f2tf(b0); bhi[g][1] = f2tf(b1);
            blo[g][0] = f2tf(b0 - __uint_as_float(bhi[g][0]));
            blo[g][1] = f2tf(b1 - __uint_as_float(bhi[g][1]));
        }
#pragma unroll
        for (int f = 0; f < 4; f++)
#pragma unroll
            for (int g = 0; g < 4; g++) {
                mma8(c[f][g], ahi[f], blo[g]);
                mma8(c[f][g], alo[f], bhi[g]);
                mma8(c[f][g], ahi[f], bhi[g]);
            }
    }
}

__device__ __forceinline__ void compute_split_kA(
    const float (*As)[136], const float (*Bs)[136],
    float4 (&c)[4][4], int gid, int tig, int mw, int nw)
{
#pragma unroll
    for (int ks = 0; ks < 16; ks += 8) {
        uint32_t ahi[4][4], alo[4][4];
        uint32_t bhi[4][2], blo[4][2];
#pragma unroll
        for (int f = 0; f < 4; f++) {
            const int r = mw + f * 16 + gid;
            float a0 = As[ks + tig][r];
            float a1 = As[ks + tig][r + 8];
            float a2 = As[ks + tig + 4][r];
            float a3 = As[ks + tig + 4][r + 8];
            ahi[f][0] = f2tf(a0); ahi[f][1] = f2tf(a1);
            ahi[f][2] = f2tf(a2); ahi[f][3] = f2tf(a3);
            alo[f][0] = f2tf(a0 - __uint_as_float(ahi[f][0]));
            alo[f][1] = f2tf(a1 - __uint_as_float(ahi[f][1]));
            alo[f][2] = f2tf(a2 - __uint_as_float(ahi[f][2]));
            alo[f][3] = f2tf(a3 - __uint_as_float(ahi[f][3]));
        }
#pragma unroll
        for (int g = 0; g < 4; g++) {
            const int n0 = nw + g * 8 + gid;
            float b0 = Bs[ks + tig][n0];
            float b1 = Bs[ks + tig + 4][n0];
            bhi[g][0] = f2tf(b0); bhi[g][1] = f2tf(b1);
            blo[g][0] = f2tf(b0 - __uint_as_float(bhi[g][0]));
            blo[g][1] = f2tf(b1 - __uint_as_float(bhi[g][1]));
        }
#pragma unroll
        for (int f = 0; f < 4; f++)
#pragma unroll
            for (int g = 0; g < 4; g++) {
                mma8(c[f][g], ahi[f], blo[g]);
                mma8(c[f][g], alo[f], bhi[g]);
                mma8(c[f][g], ahi[f], bhi[g]);
            }
    }
}

// ---------------------------------------------------------------------------
// K0: round x and Wv to tf32 (rna) once -> unbiased raw-consumption later.
// ---------------------------------------------------------------------------
__global__ __launch_bounds__(256) void round_x_kernel(const float* __restrict__ x)
{
    const size_t i = ((size_t)blockIdx.x * 256 + threadIdx.x) * 4;
    float4 v = *(const float4*)(x + i);
    v.x = __uint_as_float(f2tf(v.x));
    v.y = __uint_as_float(f2tf(v.y));
    v.z = __uint_as_float(f2tf(v.z));
    v.w = __uint_as_float(f2tf(v.w));
    *(float4*)(d_xr + i) = v;
}

__global__ __launch_bounds__(256) void round_wv_kernel(const float* __restrict__ Wv)
{
    const size_t i = ((size_t)blockIdx.x * 256 + threadIdx.x) * 4;
    float4 v = *(const float4*)(Wv + i);
    v.x = __uint_as_float(f2tf(v.x));
    v.y = __uint_as_float(f2tf(v.y));
    v.z = __uint_as_float(f2tf(v.z));
    v.w = __uint_as_float(f2tf(v.w));
    *(float4*)(d_Wvr + i) = v;
}

// ---------------------------------------------------------------------------
// K1a: f,g projection (rows 0..127 of Y) = [Wq;Wk] @ x.  SPLIT tf32, cp.async.
// ---------------------------------------------------------------------------
__global__ __launch_bounds__(256) void qkv_fg_gemm(
    const float* __restrict__ x,
    const float* __restrict__ Wq,
    const float* __restrict__ Wk)
{
    __shared__ float As[2][128][20];
    __shared__ float Bs[2][16][136];

    const int b = blockIdx.z;
    const int col0 = blockIdx.x * 128;
    const float* xb = x + (size_t)b * CC * NN;

    const int tid = threadIdx.x, lane = tid & 31, warp = tid >> 5;
    const int gid = lane >> 2, tig = lane & 3;
    const int mw = (warp >> 2) * 64, nw = (warp & 3) * 32;

    const int am0 = tid >> 2;          // 0..63
    const int ak  = (tid & 3) * 4;     // 0,4,8,12
    const float* arow0 = Wq + (size_t)am0 * CC;
    const float* arow1 = Wk + (size_t)am0 * CC;
    const int bk0 = tid >> 5;          // 0..7
    const int bn  = (tid & 31) * 4;

    float4 c[4][4];
#pragma unroll
    for (int f = 0; f < 4; f++)
#pragma unroll
        for (int g = 0; g < 4; g++) c[f][g] = make_float4(0, 0, 0, 0);

    // prologue stage 0
    cp16(&As[0][am0][ak],       arow0 + ak);
    cp16(&As[0][am0 + 64][ak],  arow1 + ak);
    cp16(&Bs[0][bk0][bn],       xb + (size_t)bk0 * NN + col0 + bn);
    cp16(&Bs[0][bk0 + 8][bn],   xb + (size_t)(bk0 + 8) * NN + col0 + bn);
    CP_COMMIT();
    CP_WAIT0();
    __syncthreads();

    const int NS = CC / 16;   // 32
    for (int s = 0; s < NS; s++) {
        const int buf = s & 1;
        if (s + 1 < NS) {
            const int kc = (s + 1) * 16;
            const int nb = buf ^ 1;
            cp16(&As[nb][am0][ak],      arow0 + kc + ak);
            cp16(&As[nb][am0 + 64][ak], arow1 + kc + ak);
            cp16(&Bs[nb][bk0][bn],      xb + (size_t)(kc + bk0) * NN + col0 + bn);
            cp16(&Bs[nb][bk0 + 8][bn],  xb + (size_t)(kc + bk0 + 8) * NN + col0 + bn);
            CP_COMMIT();
        }
        compute_split_mA(As[buf], Bs[buf], c, gid, tig, mw, nw);
        CP_WAIT0();
        __syncthreads();
    }

    float* yb = d_Y + (size_t)b * RTOT * NN;
#pragma unroll
    for (int f = 0; f < 4; f++) {
        const int r = mw + f * 16 + gid;
#pragma unroll
        for (int g = 0; g < 4; g++) {
            const int col = col0 + nw + g * 8 + 2 * tig;
            *(float2*)(yb + (size_t)r * NN + col)       = make_float2(c[f][g].x, c[f][g].y);
            *(float2*)(yb + (size_t)(r + 8) * NN + col) = make_float2(c[f][g].z, c[f][g].w);
        }
    }
}

// ---------------------------------------------------------------------------
// K1b: h' = (Wvr @ xr) * mask[col], tf32-rounded on store. Raw MMA, cp.async.
// ---------------------------------------------------------------------------
__global__ __launch_bounds__(256) void qkv_h_gemm(const float* __restrict__ mask)
{
    __shared__ float As[2][128][20];
    __shared__ float Bs[2][16][136];

    const int b = blockIdx.z;
    const int row0 = blockIdx.y * 128;
    const int col0 = blockIdx.x * 128;
    const float* xb = d_xr + (size_t)b * CC * NN;

    const int tid = threadIdx.x, lane = tid & 31, warp = tid >> 5;
    const int gid = lane >> 2, tig = lane & 3;
    const int mw = (warp >> 2) * 64, nw = (warp & 3) * 32;

    const int am0 = tid >> 2;
    const int ak  = (tid & 3) * 4;
    const float* arow0 = d_Wvr + (size_t)(row0 + am0) * CC;
    const float* arow1 = d_Wvr + (size_t)(row0 + am0 + 64) * CC;
    const int bk0 = tid >> 5;
    const int bn  = (tid & 31) * 4;

    float4 c[4][4];
#pragma unroll
    for (int f = 0; f < 4; f++)
#pragma unroll
        for (int g = 0; g < 4; g++) c[f][g] = make_float4(0, 0, 0, 0);

    cp16(&As[0][am0][ak],      arow0 + ak);
    cp16(&As[0][am0 + 64][ak], arow1 + ak);
    cp16(&Bs[0][bk0][bn],      xb + (size_t)bk0 * NN + col0 + bn);
    cp16(&Bs[0][bk0 + 8][bn],  xb + (size_t)(bk0 + 8) * NN + col0 + bn);
    CP_COMMIT();
    CP_WAIT0();
    __syncthreads();

    const int NS = CC / 16;
    for (int s = 0; s < NS; s++) {
        const int buf = s & 1;
        if (s + 1 < NS) {
            const int kc = (s + 1) * 16;
            const int nb = buf ^ 1;
            cp16(&As[nb][am0][ak],      arow0 + kc + ak);
            cp16(&As[nb][am0 + 64][ak], arow1 + kc + ak);
            cp16(&Bs[nb][bk0][bn],      xb + (size_t)(kc + bk0) * NN + col0 + bn);
            cp16(&Bs[nb][bk0 + 8][bn],  xb + (size_t)(kc + bk0 + 8) * NN + col0 + bn);
            CP_COMMIT();
        }
        compute_raw(As[buf], Bs[buf], c, gid, tig, mw, nw);
        CP_WAIT0();
        __syncthreads();
    }

    float* yb = d_Y + (size_t)b * RTOT * NN + (size_t)(2 * CQ + row0) * NN;
    const float* mb = mask + (size_t)b * NN;
#pragma unroll
    for (int f = 0; f < 4; f++) {
        const int r = mw + f * 16 + gid;
#pragma unroll
        for (int g = 0; g < 4; g++) {
            const int col = col0 + nw + g * 8 + 2 * tig;
            float2 mv = *(const float2*)(mb + col);
            float2 o0, o1;
            o0.x = __uint_as_float(f2tf(c[f][g].x * mv.x));
            o0.y = __uint_as_float(f2tf(c[f][g].y * mv.y));
            o1.x = __uint_as_float(f2tf(c[f][g].z * mv.x));
            o1.y = __uint_as_float(f2tf(c[f][g].w * mv.y));
            *(float2*)(yb + (size_t)r * NN + col)       = o0;
            *(float2*)(yb + (size_t)(r + 8) * NN + col) = o1;
        }
    }
}

// ---------------------------------------------------------------------------
// K2: E[i][j] = tf32_round(exp(leaky(F^T G))), K=64, SPLIT tf32, cp.async.
// Emits per-i-tile column partial sums of Z and mask*E.
// ---------------------------------------------------------------------------
__global__ __launch_bounds__(256) void scores_gemm_t(const float* __restrict__ mask)
{
    __shared__ float As[2][16][136];
    __shared__ float Bs[2][16][136];
    __shared__ float sZ[128];
    __shared__ float sSm[128];

    const int b  = blockIdx.z;
    const int it = blockIdx.y;
    const int i0 = it * 128;
    const int j0 = blockIdx.x * 128;
    const float* F = d_Y + (size_t)b * RTOT * NN;
    const float* G = F + (size_t)CQ * NN;

    const int tid = threadIdx.x, lane = tid & 31, warp = tid >> 5;
    const int gid = lane >> 2, tig = lane & 3;
    const int mw = (warp >> 2) * 64, nw = (warp & 3) * 32;
    const int bk0 = tid >> 5;
    const int bn  = (tid & 31) * 4;

    if (tid < 128) { sZ[tid] = 0.0f; sSm[tid] = 0.0f; }

    float4 c[4][4];
#pragma unroll
    for (int f = 0; f < 4; f++)
#pragma unroll
        for (int g = 0; g < 4; g++) c[f][g] = make_float4(0, 0, 0, 0);

    cp16(&As[0][bk0][bn],     F + (size_t)bk0 * NN + i0 + bn);
    cp16(&As[0][bk0 + 8][bn], F + (size_t)(bk0 + 8) * NN + i0 + bn);
    cp16(&Bs[0][bk0][bn],     G + (size_t)bk0 * NN + j0 + bn);
    cp16(&Bs[0][bk0 + 8][bn], G + (size_t)(bk0 + 8) * NN + j0 + bn);
    CP_COMMIT();
    CP_WAIT0();
    __syncthreads();

    const int NS = CQ / 16;  // 4
    for (int s = 0; s < NS; s++) {
        const int buf = s & 1;
        if (s + 1 < NS) {
            const int kc = (s + 1) * 16;
            const int nb = buf ^ 1;
            cp16(&As[nb][bk0][bn],     F + (size_t)(kc + bk0) * NN + i0 + bn);
            cp16(&As[nb][bk0 + 8][bn], F + (size_t)(kc + bk0 + 8) * NN + i0 + bn);
            cp16(&Bs[nb][bk0][bn],     G + (size_t)(kc + bk0) * NN + j0 + bn);
            cp16(&Bs[nb][bk0 + 8][bn], G + (size_t)(kc + bk0 + 8) * NN + j0 + bn);
            CP_COMMIT();
        }
        compute_split_kA(As[buf], Bs[buf], c, gid, tig, mw, nw);
        CP_WAIT0();
        __syncthreads();
    }

    float* S = d_scores + (size_t)b * NN * NN;
    const float* mb = mask + (size_t)b * NN;

    float mrow[4][2];
#pragma unroll
    for (int f = 0; f < 4; f++) {
        const int r = i0 + mw + f * 16 + gid;
        mrow[f][0] = __ldg(&mb[r]);
        mrow[f][1] = __ldg(&mb[r + 8]);
    }

#pragma unroll
    for (int g = 0; g < 4; g++) {
        const int colL = nw + g * 8 + 2 * tig;
        float z0 = 0, z1 = 0, sm0 = 0, sm1 = 0;
#pragma unroll
        for (int f = 0; f < 4; f++) {
            const int r = i0 + mw + f * 16 + gid;
            float s0 = c[f][g].x, s1 = c[f][g].y, s2 = c[f][g].z, s3 = c[f][g].w;
            s0 = s0 >= 0.0f ? s0 : 0.2f * s0;
            s1 = s1 >= 0.0f ? s1 : 0.2f * s1;
            s2 = s2 >= 0.0f ? s2 : 0.2f * s2;
            s3 = s3 >= 0.0f ? s3 : 0.2f * s3;
            float e0 = __expf(fminf(s0, 75.0f));
            float e1 = __expf(fminf(s1, 75.0f));
            float e2 = __expf(fminf(s2, 75.0f));
            float e3 = __expf(fminf(s3, 75.0f));
            *(float2*)(S + (size_t)r * NN + j0 + colL) =
                make_float2(__uint_as_float(f2tf(e0)), __uint_as_float(f2tf(e1)));
            *(float2*)(S + (size_t)(r + 8) * NN + j0 + colL) =
                make_float2(__uint_as_float(f2tf(e2)), __uint_as_float(f2tf(e3)));
            z0 += e0 + e2;   z1 += e1 + e3;
            sm0 += mrow[f][0] * e0 + mrow[f][1] * e2;
            sm1 += mrow[f][0] * e1 + mrow[f][1] * e3;
        }
        atomicAdd(&sZ[colL], z0);       atomicAdd(&sZ[colL + 1], z1);
        atomicAdd(&sSm[colL], sm0);     atomicAdd(&sSm[colL + 1], sm1);
    }
    __syncthreads();
    if (tid < 128) {
        const size_t off = ((size_t)b * 8 + it) * NN + j0 + tid;
        d_partZ[off]  = sZ[tid];
        d_partSm[off] = sSm[tid];
    }
}

// ---------------------------------------------------------------------------
// K2b: fold 8 i-tile partials into column sums.
// ---------------------------------------------------------------------------
__global__ __launch_bounds__(256) void reduce_sums()
{
    const int b = blockIdx.y;
    const int j = blockIdx.x * 256 + threadIdx.x;
    float z = 0.0f, s = 0.0f;
#pragma unroll
    for (int t = 0; t < 8; t++) {
        const size_t off = ((size_t)b * 8 + t) * NN + j;
        z += d_partZ[off];
        s += d_partSm[off];
    }
    d_colZ[(size_t)b * NN + j]  = z;
    d_colSm[(size_t)b * NN + j] = s;
}

// ---------------------------------------------------------------------------
// K4: out[c][m] = gamma*(sum_n h'[c][n]*E[n][m])*mask[m]/(Sm+eps*Z) + x[c][m]
// Raw MMA (operands already tf32), cp.async.
// ---------------------------------------------------------------------------
__global__ __launch_bounds__(256) void out_gemm_t(
    const float* __restrict__ x,
    const float* __restrict__ mask,
    const float* __restrict__ gamma,
    float* __restrict__ out)
{
    __shared__ float As[2][128][20];
    __shared__ float Bs[2][16][136];

    const int b  = blockIdx.z;
    const int c0 = blockIdx.y * 128;
    const int m0 = blockIdx.x * 128;
    const float* h  = d_Y + (size_t)b * RTOT * NN + (size_t)(2 * CQ) * NN;
    const float* Bt = d_scores + (size_t)b * NN * NN;

    const int tid = threadIdx.x, lane = tid & 31, warp = tid >> 5;
    const int gid = lane >> 2, tig = lane & 3;
    const int mw = (warp >> 2) * 64, nw = (warp & 3) * 32;

    const int am0 = tid >> 2;
    const int ak  = (tid & 3) * 4;
    const float* arow0 = h + (size_t)(c0 + am0) * NN;
    const float* arow1 = h + (size_t)(c0 + am0 + 64) * NN;
    const int bk0 = tid >> 5;
    const int bn  = (tid & 31) * 4;

    float4 c[4][4];
#pragma unroll
    for (int f = 0; f < 4; f++)
#pragma unroll
        for (int g = 0; g < 4; g++) c[f][g] = make_float4(0, 0, 0, 0);

    cp16(&As[0][am0][ak],      arow0 + ak);
    cp16(&As[0][am0 + 64][ak], arow1 + ak);
    cp16(&Bs[0][bk0][bn],      Bt + (size_t)bk0 * NN + m0 + bn);
    cp16(&Bs[0][bk0 + 8][bn],  Bt + (size_t)(bk0 + 8) * NN + m0 + bn);
    CP_COMMIT();
    CP_WAIT0();
    __syncthreads();

    const int NS = NN / 16;  // 64
    for (int s = 0; s < NS; s++) {
        const int buf = s & 1;
        if (s + 1 < NS) {
            const int kc = (s + 1) * 16;
            const int nb = buf ^ 1;
            cp16(&As[nb][am0][ak],      arow0 + kc + ak);
            cp16(&As[nb][am0 + 64][ak], arow1 + kc + ak);
            cp16(&Bs[nb][bk0][bn],      Bt + (size_t)(kc + bk0) * NN + m0 + bn);
            cp16(&Bs[nb][bk0 + 8][bn],  Bt + (size_t)(kc + bk0 + 8) * NN + m0 + bn);
            CP_COMMIT();
        }
        compute_raw(As[buf], Bs[buf], c, gid, tig, mw, nw);
        CP_WAIT0();
        __syncthreads();
    }

    const float g0 = gamma[0];
    const float* xb = x + (size_t)b * CC * NN;
    float* ob = out + (size_t)b * CC * NN;
    const float* mb = mask + (size_t)b * NN;
    const float* zc = d_colZ + (size_t)b * NN;
    const float* sc = d_colSm + (size_t)b * NN;

#pragma unroll
    for (int g = 0; g < 4; g++) {
        const int col = m0 + nw + g * 8 + 2 * tig;
        float2 mv = *(const float2*)(mb + col);
        float2 zv = *(const float2*)(zc + col);
        float2 sv = *(const float2*)(sc + col);
        const float w0 = g0 * mv.x / (sv.x + 1e-6f * zv.x);
        const float w1 = g0 * mv.y / (sv.y + 1e-6f * zv.y);
#pragma unroll
        for (int f = 0; f < 4; f++) {
            const int r = c0 + mw + f * 16 + gid;
            float2 x0 = *(const float2*)(xb + (size_t)r * NN + col);
            float2 x1 = *(const float2*)(xb + (size_t)(r + 8) * NN + col);
            float2 o0, o1;
            o0.x = c[f][g].x * w0 + x0.x;
            o0.y = c[f][g].y * w1 + x0.y;
            o1.x = c[f][g].z * w0 + x1.x;
            o1.y = c[f][g].w * w1 + x1.y;
            *(float2*)(ob + (size_t)r * NN + col)       = o0;
            *(float2*)(ob + (size_t)(r + 8) * NN + col) = o1;
        }
    }
}

// ---------------------------------------------------------------------------
extern "C" void kernel_launch(void* const* d_in, const int* in_sizes, int n_in,
                              void* d_out, int out_size)
{
    const float* x     = (const float*)d_in[0];
    const float* mask  = (const float*)d_in[1];
    const float* Wq    = (const float*)d_in[2];
    const float* Wk    = (const float*)d_in[3];
    const float* Wv    = (const float*)d_in[4];
    const float* gamma = (const float*)d_in[5];
    float* out = (float*)d_out;

    round_x_kernel <<<(size_t)BB * CC * NN / (256 * 4), 256>>>(x);
    round_wv_kernel<<<(size_t)CC * CC / (256 * 4), 256>>>(Wv);
    qkv_fg_gemm<<<dim3(NN / 128, 1, BB), 256>>>(x, Wq, Wk);
    qkv_h_gemm<<<dim3(NN / 128, 4, BB), 256>>>(mask);
    scores_gemm_t<<<dim3(NN / 128, NN / 128, BB), 256>>>(mask);
    reduce_sums<<<dim3(NN / 256, BB), 256>>>();
    out_gemm_t<<<dim3(NN / 128, CC / 128, BB), 256>>>(x, mask, gamma, out);
}